// round 1
// baseline (speedup 1.0000x reference)
#include <cuda_runtime.h>
#include <cstdint>
#include <math.h>

// Problem constants
#define E_DIM 1024
#define C_DIM 1024
#define H_DIM 4096
#define V_DIM 32000
#define L_NUM 6
#define N_TOK 4096
#define LN_EPS 1e-5f

// ---------------------------------------------------------------------------
// Scratch (static device globals — no allocation allowed)
// g_xc holds [x | context] per token: [N_TOK, 2048]. x written once,
// context half updated each layer (concat-free W1 GEMM).
// ---------------------------------------------------------------------------
__device__ float g_xc[(size_t)N_TOK * 2048];
__device__ float g_hidden[(size_t)N_TOK * H_DIM];
__device__ float g_dd[(size_t)N_TOK * C_DIM];
__device__ float g_ff[(size_t)N_TOK * C_DIM];
__device__ float g_ii[(size_t)N_TOK * C_DIM];

// ---------------------------------------------------------------------------
// tf32 helpers
// ---------------------------------------------------------------------------
__device__ __forceinline__ float f2tf(float x) {
    uint32_t r;
    asm("cvt.rna.tf32.f32 %0, %1;" : "=r"(r) : "f"(x));
    return __uint_as_float(r);
}

__device__ __forceinline__ void mma8(float* d, const uint32_t* a, const uint32_t* b) {
    asm volatile(
        "mma.sync.aligned.m16n8k8.row.col.f32.tf32.tf32.f32 "
        "{%0,%1,%2,%3}, {%4,%5,%6,%7}, {%8,%9}, {%0,%1,%2,%3};\n"
        : "+f"(d[0]), "+f"(d[1]), "+f"(d[2]), "+f"(d[3])
        : "r"(a[0]), "r"(a[1]), "r"(a[2]), "r"(a[3]),
          "r"(b[0]), "r"(b[1]));
}

// ---------------------------------------------------------------------------
// Generic tf32 tensor-core GEMM:  C[M,N] = act(A[M,K] @ B[K,N] + bias)
// A row-major with explicit lda (lets us read the x-half of g_xc with K=1024).
// B row-major [K,N] (weights are stored [in,out]).
// Tiles: 128x128x32, 256 threads, 8 warps of 64x32. All dims divisible.
// ---------------------------------------------------------------------------
__global__ __launch_bounds__(256) void gemm_tf32(
    const float* __restrict__ A, int lda,
    const float* __restrict__ B,
    const float* __restrict__ bias,
    float* __restrict__ C,
    int M, int N, int K, int doRelu)
{
    __shared__ float sA[128][36];   // pad 4: frag reads conflict-free
    __shared__ float sB[32][136];   // pad 8: frag reads conflict-free

    const int tid  = threadIdx.x;
    const int lane = tid & 31;
    const int g    = lane >> 2;     // groupID 0..7
    const int t4   = lane & 3;      // threadID_in_group 0..3
    const int warp = tid >> 5;
    const int mW   = (warp >> 2) * 64;   // 2 warps in M
    const int nW   = (warp & 3) * 32;    // 4 warps in N

    const size_t mOff = (size_t)blockIdx.y * 128;
    const size_t nOff = (size_t)blockIdx.x * 128;
    const float* Ab = A + mOff * (size_t)lda;
    const float* Bb = B + nOff;

    float acc[4][4][4];
    #pragma unroll
    for (int i = 0; i < 4; i++)
        #pragma unroll
        for (int j = 0; j < 4; j++)
            #pragma unroll
            for (int r = 0; r < 4; r++) acc[i][j][r] = 0.f;

    const int nkt = K >> 5;
    for (int kt = 0; kt < nkt; ++kt) {
        // Load A tile 128x32 (tf32-round once here, reuse from smem)
        #pragma unroll
        for (int i = 0; i < 4; i++) {
            int lin = tid + (i << 8);
            int r = lin >> 3, c4 = (lin & 7) << 2;
            float4 v = *reinterpret_cast<const float4*>(
                Ab + (size_t)r * lda + (kt << 5) + c4);
            float4 w;
            w.x = f2tf(v.x); w.y = f2tf(v.y); w.z = f2tf(v.z); w.w = f2tf(v.w);
            *reinterpret_cast<float4*>(&sA[r][c4]) = w;
        }
        // Load B tile 32x128
        #pragma unroll
        for (int i = 0; i < 4; i++) {
            int lin = tid + (i << 8);
            int r = lin >> 5, c4 = (lin & 31) << 2;
            float4 v = *reinterpret_cast<const float4*>(
                Bb + (size_t)((kt << 5) + r) * N + c4);
            float4 w;
            w.x = f2tf(v.x); w.y = f2tf(v.y); w.z = f2tf(v.z); w.w = f2tf(v.w);
            *reinterpret_cast<float4*>(&sB[r][c4]) = w;
        }
        __syncthreads();

        #pragma unroll
        for (int ks = 0; ks < 4; ++ks) {
            uint32_t af[4][4];
            uint32_t bfr[4][2];
            #pragma unroll
            for (int mt = 0; mt < 4; ++mt) {
                int rb = mW + mt * 16;
                int kc = ks * 8 + t4;
                af[mt][0] = __float_as_uint(sA[rb + g][kc]);
                af[mt][1] = __float_as_uint(sA[rb + g + 8][kc]);
                af[mt][2] = __float_as_uint(sA[rb + g][kc + 4]);
                af[mt][3] = __float_as_uint(sA[rb + g + 8][kc + 4]);
            }
            #pragma unroll
            for (int nt = 0; nt < 4; ++nt) {
                int cb = nW + nt * 8 + g;
                bfr[nt][0] = __float_as_uint(sB[ks * 8 + t4][cb]);
                bfr[nt][1] = __float_as_uint(sB[ks * 8 + t4 + 4][cb]);
            }
            #pragma unroll
            for (int mt = 0; mt < 4; ++mt)
                #pragma unroll
                for (int nt = 0; nt < 4; ++nt)
                    mma8(acc[mt][nt], af[mt], bfr[nt]);
        }
        __syncthreads();
    }

    // Epilogue: bias + optional relu
    #pragma unroll
    for (int mt = 0; mt < 4; ++mt) {
        size_t r0 = mOff + mW + mt * 16 + g;
        #pragma unroll
        for (int nt = 0; nt < 4; ++nt) {
            size_t c0 = nOff + nW + nt * 8 + (t4 << 1);
            float b0 = bias[c0], b1v = bias[c0 + 1];
            float v0 = acc[mt][nt][0] + b0;
            float v1 = acc[mt][nt][1] + b1v;
            float v2 = acc[mt][nt][2] + b0;
            float v3 = acc[mt][nt][3] + b1v;
            if (doRelu) {
                v0 = fmaxf(v0, 0.f); v1 = fmaxf(v1, 0.f);
                v2 = fmaxf(v2, 0.f); v3 = fmaxf(v3, 0.f);
            }
            C[r0 * N + c0]           = v0;
            C[r0 * N + c0 + 1]       = v1;
            C[(r0 + 8) * N + c0]     = v2;
            C[(r0 + 8) * N + c0 + 1] = v3;
        }
    }
}

// ---------------------------------------------------------------------------
// Block reduction over 256 threads
// ---------------------------------------------------------------------------
__device__ __forceinline__ float block_sum(float v) {
    __shared__ float sbuf[8];
    #pragma unroll
    for (int o = 16; o; o >>= 1) v += __shfl_xor_sync(0xffffffffu, v, o);
    if ((threadIdx.x & 31) == 0) sbuf[threadIdx.x >> 5] = v;
    __syncthreads();
    if (threadIdx.x < 32) {
        float s = (threadIdx.x < 8) ? sbuf[threadIdx.x] : 0.f;
        #pragma unroll
        for (int o = 4; o; o >>= 1) s += __shfl_xor_sync(0xffffffffu, s, o);
        if (threadIdx.x == 0) sbuf[0] = s;
    }
    __syncthreads();
    float r = sbuf[0];
    __syncthreads();
    return r;
}

// ---------------------------------------------------------------------------
// Embedding gather + LayerNorm -> x half of g_xc; zero the context half.
// One block per token, 256 threads, 4 elems/thread (E=1024).
// ---------------------------------------------------------------------------
__global__ __launch_bounds__(256) void embed_ln_kernel(
    const int* __restrict__ ids, const float* __restrict__ emb,
    const float* __restrict__ gw, const float* __restrict__ bw)
{
    int n = blockIdx.x;
    const float* row = emb + (size_t)ids[n] * E_DIM;
    float v[4];
    float s = 0.f;
    #pragma unroll
    for (int i = 0; i < 4; i++) {
        v[i] = row[threadIdx.x + (i << 8)];
        s += v[i];
    }
    float mean = block_sum(s) * (1.f / E_DIM);
    float q = 0.f;
    #pragma unroll
    for (int i = 0; i < 4; i++) { float d = v[i] - mean; q += d * d; }
    float var = block_sum(q) * (1.f / E_DIM);
    float rstd = rsqrtf(var + LN_EPS);
    float* out = g_xc + (size_t)n * 2048;
    #pragma unroll
    for (int i = 0; i < 4; i++) {
        int j = threadIdx.x + (i << 8);
        out[j] = (v[i] - mean) * rstd * gw[j] + bw[j];
        out[1024 + j] = 0.f;  // context init (rewritten every call: deterministic)
    }
}

// ---------------------------------------------------------------------------
// Gate activations + context update + LayerNorm + clip, in-place into the
// context half of g_xc. One block per token.
// ---------------------------------------------------------------------------
__global__ __launch_bounds__(256) void ctx_kernel(
    const float* __restrict__ dd, const float* __restrict__ ff,
    const float* __restrict__ ii,
    const float* __restrict__ gw, const float* __restrict__ bw)
{
    int n = blockIdx.x;
    size_t o = (size_t)n * C_DIM;
    float* ctx = g_xc + (size_t)n * 2048 + 1024;
    float v[4];
    float s = 0.f;
    #pragma unroll
    for (int i = 0; i < 4; i++) {
        int j = threadIdx.x + (i << 8);
        float d  = tanhf(dd[o + j]);
        float fg = 1.f / (1.f + expf(-ff[o + j]));
        float ig = 1.f / (1.f + expf(-ii[o + j]));
        v[i] = fg * ctx[j] + ig * d;
        s += v[i];
    }
    float mean = block_sum(s) * (1.f / C_DIM);
    float q = 0.f;
    #pragma unroll
    for (int i = 0; i < 4; i++) { float d = v[i] - mean; q += d * d; }
    float var = block_sum(q) * (1.f / C_DIM);
    float rstd = rsqrtf(var + LN_EPS);
    #pragma unroll
    for (int i = 0; i < 4; i++) {
        int j = threadIdx.x + (i << 8);
        float ov = (v[i] - mean) * rstd * gw[j] + bw[j];
        ctx[j] = fminf(fmaxf(ov, -10.f), 10.f);
    }
}

// ---------------------------------------------------------------------------
// Launch: embed -> 6x { W1 gemm(+relu), [gates + ctx update for l<5] } -> head
// ---------------------------------------------------------------------------
extern "C" void kernel_launch(void* const* d_in, const int* in_sizes, int n_in,
                              void* d_out, int out_size)
{
    (void)in_sizes; (void)n_in; (void)out_size;
    const int*   ids  = (const int*)d_in[0];
    const float* emb  = (const float*)d_in[1];
    const float* en_g = (const float*)d_in[2];
    const float* en_b = (const float*)d_in[3];
    const float* W1   = (const float*)d_in[4];
    const float* b1   = (const float*)d_in[5];
    const float* Wd   = (const float*)d_in[6];
    const float* bd   = (const float*)d_in[7];
    const float* Wf   = (const float*)d_in[8];
    const float* bff  = (const float*)d_in[9];
    const float* Wi   = (const float*)d_in[10];
    const float* bi   = (const float*)d_in[11];
    const float* lng  = (const float*)d_in[12];
    const float* lnb  = (const float*)d_in[13];
    const float* Wout = (const float*)d_in[14];
    const float* bout = (const float*)d_in[15];
    float* out = (float*)d_out;

    float *xc, *hid, *dd, *ff, *ii;
    cudaGetSymbolAddress((void**)&xc,  g_xc);
    cudaGetSymbolAddress((void**)&hid, g_hidden);
    cudaGetSymbolAddress((void**)&dd,  g_dd);
    cudaGetSymbolAddress((void**)&ff,  g_ff);
    cudaGetSymbolAddress((void**)&ii,  g_ii);

    embed_ln_kernel<<<N_TOK, 256>>>(ids, emb, en_g, en_b);

    dim3 gH(H_DIM / 128, N_TOK / 128);   // (32, 32)
    dim3 gC(C_DIM / 128, N_TOK / 128);   // (8, 32)
    dim3 gV(V_DIM / 128, N_TOK / 128);   // (250, 32)

    for (int l = 0; l < L_NUM; l++) {
        const float* W1l = W1 + (size_t)l * 2048 * H_DIM;
        const float* b1l = b1 + (size_t)l * H_DIM;
        // layer 0: context is zero -> only the x half of K contributes
        int Keff = (l == 0) ? E_DIM : 2048;
        gemm_tf32<<<gH, 256>>>(xc, 2048, W1l, b1l, hid, N_TOK, H_DIM, Keff, 1);

        if (l < L_NUM - 1) {  // layer 5's context update never feeds the logits
            gemm_tf32<<<gC, 256>>>(hid, H_DIM, Wd + (size_t)l * H_DIM * C_DIM,
                                   bd + (size_t)l * C_DIM, dd,
                                   N_TOK, C_DIM, H_DIM, 0);
            gemm_tf32<<<gC, 256>>>(hid, H_DIM, Wf + (size_t)l * H_DIM * C_DIM,
                                   bff + (size_t)l * C_DIM, ff,
                                   N_TOK, C_DIM, H_DIM, 0);
            gemm_tf32<<<gC, 256>>>(hid, H_DIM, Wi + (size_t)l * H_DIM * C_DIM,
                                   bi + (size_t)l * C_DIM, ii,
                                   N_TOK, C_DIM, H_DIM, 0);
            ctx_kernel<<<N_TOK, 256>>>(dd, ff, ii,
                                       lng + (size_t)l * C_DIM,
                                       lnb + (size_t)l * C_DIM);
        }
    }

    gemm_tf32<<<gV, 256>>>(hid, H_DIM, Wout, bout, out, N_TOK, V_DIM, H_DIM, 0);
}

// round 3
// speedup vs baseline: 2.9747x; 2.9747x over previous
#include <cuda_runtime.h>
#include <cuda_fp16.h>
#include <cstdint>
#include <math.h>

#define E_DIM 1024
#define C_DIM 1024
#define H_DIM 4096
#define V_DIM 32000
#define L_NUM 6
#define N_TOK 4096
#define LN_EPS 1e-5f

// ---------------------------------------------------------------------------
// Static device scratch (no allocation allowed)
// ---------------------------------------------------------------------------
__device__ __half g_W1T[(size_t)L_NUM * H_DIM * 2048];     // [L][4096][2048] K-major
__device__ __half g_WgT[(size_t)L_NUM * 3072 * H_DIM];     // [L][3072][4096] (d|f|i)
__device__ __half g_WoutT[(size_t)V_DIM * H_DIM];          // [32000][4096]
__device__ __half g_xc[(size_t)N_TOK * 2048];              // [x | ctx] fp16 GEMM A
__device__ __half g_hidden[(size_t)N_TOK * H_DIM];         // fp16 GEMM A
__device__ float  g_ctx[(size_t)N_TOK * C_DIM];            // fp32 recurrence
__device__ float  g_gates[(size_t)N_TOK * 3072];           // gate pre-activations
__device__ float  g_bg[3072];                              // concat gate bias

__device__ __forceinline__ uint32_t smem_u32(const void* p) {
    uint32_t a;
    asm("{ .reg .u64 t; cvta.to.shared.u64 t, %1; cvt.u32.u64 %0, t; }" : "=r"(a) : "l"(p));
    return a;
}

// ---------------------------------------------------------------------------
// GEMM: C[M,N] = act(A[M,K] @ B^T + bias), A row-major fp16 (lda),
// B fp16 [N][K] K-major (ldb). CTA tile 128x128x64, 3-stage cp.async,
// ldmatrix + mma.sync m16n8k16 (fp32 accum). 8 warps = 2(M) x 4(N) of 64x32.
// ---------------------------------------------------------------------------
#define BK 64
#define STAGE_BYTES 32768u     // A 16KB + B 16KB
#define SMEM_GEMM   98304      // 3 stages

__device__ __forceinline__ void cp16(uint32_t d, const void* g) {
    asm volatile("cp.async.cg.shared.global [%0], [%1], 16;\n" :: "r"(d), "l"(g) : "memory");
}
__device__ __forceinline__ void cp_commit() {
    asm volatile("cp.async.commit_group;\n" ::: "memory");
}

__device__ __forceinline__ void load_stage(
    uint32_t sb, int s, const __half* __restrict__ Ab, int lda,
    const __half* __restrict__ Bb, int ldb, int kt, int tid)
{
    uint32_t base = sb + (uint32_t)s * STAGE_BYTES;
    int k0 = kt * BK;
    #pragma unroll
    for (int j = 0; j < 4; j++) {           // A: 128 rows x 8 chunks
        int i = tid + (j << 8);
        int r = i >> 3, c = i & 7;
        cp16(base + (r << 7) + ((uint32_t)(c ^ (r & 7)) << 4),
             Ab + (size_t)r * lda + k0 + (c << 3));
    }
    #pragma unroll
    for (int j = 0; j < 4; j++) {           // B: 128 rows x 8 chunks
        int i = tid + (j << 8);
        int r = i >> 3, c = i & 7;
        cp16(base + 16384u + (r << 7) + ((uint32_t)(c ^ (r & 7)) << 4),
             Bb + (size_t)r * ldb + k0 + (c << 3));
    }
    cp_commit();
}

__global__ __launch_bounds__(256, 2) void gemm_hmma(
    const __half* __restrict__ A, int lda,
    const __half* __restrict__ B, int ldb,
    const float* __restrict__ bias,
    void* __restrict__ Cout, int ldc,
    int K, int mode)   // mode 0: fp32 out; 1: relu -> fp16 out
{
    extern __shared__ __align__(128) char smem[];
    uint32_t sb = smem_u32(smem);
    const int tid = threadIdx.x, lane = tid & 31, warp = tid >> 5;
    const int mW = (warp >> 2) * 64;       // 2 warps in M
    const int nW = (warp & 3) * 32;        // 4 warps in N

    const size_t m0 = (size_t)blockIdx.x * 128;
    const size_t n0 = (size_t)blockIdx.y * 128;
    const __half* Ab = A + m0 * (size_t)lda;
    const __half* Bb = B + n0 * (size_t)ldb;

    const int KT = K / BK;

    load_stage(sb, 0, Ab, lda, Bb, ldb, 0, tid);
    if (KT > 1) load_stage(sb, 1, Ab, lda, Bb, ldb, 1, tid);

    float acc[4][4][4];
    #pragma unroll
    for (int i = 0; i < 4; i++)
        #pragma unroll
        for (int j = 0; j < 4; j++) {
            acc[i][j][0] = 0.f; acc[i][j][1] = 0.f;
            acc[i][j][2] = 0.f; acc[i][j][3] = 0.f;
        }

    // precomputed ldmatrix lane addressing (relative offsets)
    const int a_row = mW + (lane & 15);            // + mt*16
    const int a_chk = lane >> 4;                   // + ks*2
    const int b_row = nW + (lane & 7);             // + nt*8
    const int b_chk = (lane >> 3) & 1;             // + ks*2

    for (int kt = 0; kt < KT; kt++) {
        if (kt + 1 < KT) asm volatile("cp.async.wait_group 1;\n" ::: "memory");
        else             asm volatile("cp.async.wait_group 0;\n" ::: "memory");
        __syncthreads();

        if (kt + 2 < KT)
            load_stage(sb, (kt + 2) % 3, Ab, lda, Bb, ldb, kt + 2, tid);

        uint32_t abase = sb + (uint32_t)(kt % 3) * STAGE_BYTES;
        uint32_t bbase = abase + 16384u;

        #pragma unroll
        for (int ks = 0; ks < 4; ks++) {
            uint32_t af[4][4], bf[4][2];
            #pragma unroll
            for (int mt = 0; mt < 4; mt++) {
                int r = a_row + mt * 16;
                int ch = (ks * 2 + a_chk) ^ (r & 7);
                uint32_t ad = abase + (r << 7) + (ch << 4);
                asm volatile("ldmatrix.sync.aligned.m8n8.x4.shared.b16 {%0,%1,%2,%3}, [%4];"
                    : "=r"(af[mt][0]), "=r"(af[mt][1]), "=r"(af[mt][2]), "=r"(af[mt][3])
                    : "r"(ad));
            }
            #pragma unroll
            for (int nt = 0; nt < 4; nt++) {
                int r = b_row + nt * 8;
                int ch = (ks * 2 + b_chk) ^ (r & 7);
                uint32_t bd = bbase + (r << 7) + (ch << 4);
                asm volatile("ldmatrix.sync.aligned.m8n8.x2.shared.b16 {%0,%1}, [%2];"
                    : "=r"(bf[nt][0]), "=r"(bf[nt][1]) : "r"(bd));
            }
            #pragma unroll
            for (int mt = 0; mt < 4; mt++)
                #pragma unroll
                for (int nt = 0; nt < 4; nt++)
                    asm volatile(
                        "mma.sync.aligned.m16n8k16.row.col.f32.f16.f16.f32 "
                        "{%0,%1,%2,%3}, {%4,%5,%6,%7}, {%8,%9}, {%0,%1,%2,%3};"
                        : "+f"(acc[mt][nt][0]), "+f"(acc[mt][nt][1]),
                          "+f"(acc[mt][nt][2]), "+f"(acc[mt][nt][3])
                        : "r"(af[mt][0]), "r"(af[mt][1]), "r"(af[mt][2]), "r"(af[mt][3]),
                          "r"(bf[nt][0]), "r"(bf[nt][1]));
        }
        __syncthreads();
    }

    // Epilogue: lane (l>>2)=row-in-8, (l&3)*2=col pair
    const int er = lane >> 2, ec = (lane & 3) * 2;
    #pragma unroll
    for (int mt = 0; mt < 4; mt++) {
        size_t mA = m0 + mW + mt * 16 + er;
        size_t mB = mA + 8;
        #pragma unroll
        for (int nt = 0; nt < 4; nt++) {
            size_t n = n0 + nW + nt * 8 + ec;
            float b0 = bias[n], b1 = bias[n + 1];
            float v0 = acc[mt][nt][0] + b0;
            float v1 = acc[mt][nt][1] + b1;
            float v2 = acc[mt][nt][2] + b0;
            float v3 = acc[mt][nt][3] + b1;
            if (mode == 0) {
                float* o = (float*)Cout;
                *reinterpret_cast<float2*>(o + mA * (size_t)ldc + n) = make_float2(v0, v1);
                *reinterpret_cast<float2*>(o + mB * (size_t)ldc + n) = make_float2(v2, v3);
            } else {
                __half* o = (__half*)Cout;
                v0 = fmaxf(v0, 0.f); v1 = fmaxf(v1, 0.f);
                v2 = fmaxf(v2, 0.f); v3 = fmaxf(v3, 0.f);
                *reinterpret_cast<__half2*>(o + mA * (size_t)ldc + n) = __floats2half2_rn(v0, v1);
                *reinterpret_cast<__half2*>(o + mB * (size_t)ldc + n) = __floats2half2_rn(v2, v3);
            }
        }
    }
}

// ---------------------------------------------------------------------------
// Transposing fp32 -> fp16 weight convert: out[n][k] = in[k][n]
// ---------------------------------------------------------------------------
__global__ __launch_bounds__(256) void convT(
    const float* __restrict__ in, __half* __restrict__ out, int K, int N)
{
    __shared__ float t[32][33];
    int n0 = blockIdx.x * 32, k0 = blockIdx.y * 32;
    int tx = threadIdx.x & 31, ty = threadIdx.x >> 5;
    #pragma unroll
    for (int i = 0; i < 32; i += 8)
        t[ty + i][tx] = in[(size_t)(k0 + ty + i) * N + n0 + tx];
    __syncthreads();
    #pragma unroll
    for (int i = 0; i < 32; i += 8)
        out[(size_t)(n0 + ty + i) * K + k0 + tx] = __float2half_rn(t[tx][ty + i]);
}

// ---------------------------------------------------------------------------
// Block reduction (256 threads)
// ---------------------------------------------------------------------------
__device__ __forceinline__ float block_sum(float v) {
    __shared__ float sbuf[8];
    #pragma unroll
    for (int o = 16; o; o >>= 1) v += __shfl_xor_sync(0xffffffffu, v, o);
    if ((threadIdx.x & 31) == 0) sbuf[threadIdx.x >> 5] = v;
    __syncthreads();
    if (threadIdx.x < 32) {
        float s = (threadIdx.x < 8) ? sbuf[threadIdx.x] : 0.f;
        #pragma unroll
        for (int o = 4; o; o >>= 1) s += __shfl_xor_sync(0xffffffffu, s, o);
        if (threadIdx.x == 0) sbuf[0] = s;
    }
    __syncthreads();
    float r = sbuf[0];
    __syncthreads();
    return r;
}

// ---------------------------------------------------------------------------
// Embedding gather + LN -> fp16 x; zero ctx halves
// ---------------------------------------------------------------------------
__global__ __launch_bounds__(256) void embed_ln_kernel(
    const int* __restrict__ ids, const float* __restrict__ emb,
    const float* __restrict__ gw, const float* __restrict__ bw)
{
    int n = blockIdx.x;
    const float* row = emb + (size_t)ids[n] * E_DIM;
    float v[4]; float s = 0.f;
    #pragma unroll
    for (int i = 0; i < 4; i++) { v[i] = row[threadIdx.x + (i << 8)]; s += v[i]; }
    float mean = block_sum(s) * (1.f / E_DIM);
    float q = 0.f;
    #pragma unroll
    for (int i = 0; i < 4; i++) { float d = v[i] - mean; q += d * d; }
    float rstd = rsqrtf(block_sum(q) * (1.f / E_DIM) + LN_EPS);
    __half* out = g_xc + (size_t)n * 2048;
    float* ctx = g_ctx + (size_t)n * C_DIM;
    #pragma unroll
    for (int i = 0; i < 4; i++) {
        int j = threadIdx.x + (i << 8);
        out[j] = __float2half_rn((v[i] - mean) * rstd * gw[j] + bw[j]);
        out[1024 + j] = __float2half_rn(0.f);
        ctx[j] = 0.f;
    }
}

// ---------------------------------------------------------------------------
// Gates -> context update + LN + clip
// ---------------------------------------------------------------------------
__global__ __launch_bounds__(256) void ctx_kernel(
    const float* __restrict__ gw, const float* __restrict__ bw)
{
    int n = blockIdx.x;
    const float* g = g_gates + (size_t)n * 3072;
    float* ctx = g_ctx + (size_t)n * C_DIM;
    __half* cxh = g_xc + (size_t)n * 2048 + 1024;
    float v[4]; float s = 0.f;
    #pragma unroll
    for (int i = 0; i < 4; i++) {
        int j = threadIdx.x + (i << 8);
        float d  = tanhf(g[j]);
        float fg = 1.f / (1.f + expf(-g[1024 + j]));
        float ig = 1.f / (1.f + expf(-g[2048 + j]));
        v[i] = fg * ctx[j] + ig * d;
        s += v[i];
    }
    float mean = block_sum(s) * (1.f / C_DIM);
    float q = 0.f;
    #pragma unroll
    for (int i = 0; i < 4; i++) { float d = v[i] - mean; q += d * d; }
    float rstd = rsqrtf(block_sum(q) * (1.f / C_DIM) + LN_EPS);
    #pragma unroll
    for (int i = 0; i < 4; i++) {
        int j = threadIdx.x + (i << 8);
        float ov = (v[i] - mean) * rstd * gw[j] + bw[j];
        ov = fminf(fmaxf(ov, -10.f), 10.f);
        ctx[j] = ov;
        cxh[j] = __float2half_rn(ov);
    }
}

__global__ void catbias(const float* __restrict__ bd, const float* __restrict__ bf,
                        const float* __restrict__ bi)
{
    int j = blockIdx.x * 256 + threadIdx.x;
    g_bg[j] = (j < 1024) ? bd[j] : ((j < 2048) ? bf[j - 1024] : bi[j - 2048]);
}

// ---------------------------------------------------------------------------
// Launch
// ---------------------------------------------------------------------------
extern "C" void kernel_launch(void* const* d_in, const int* in_sizes, int n_in,
                              void* d_out, int out_size)
{
    (void)in_sizes; (void)n_in; (void)out_size;
    const int*   ids  = (const int*)d_in[0];
    const float* emb  = (const float*)d_in[1];
    const float* en_g = (const float*)d_in[2];
    const float* en_b = (const float*)d_in[3];
    const float* W1   = (const float*)d_in[4];
    const float* b1   = (const float*)d_in[5];
    const float* Wd   = (const float*)d_in[6];
    const float* bd   = (const float*)d_in[7];
    const float* Wf   = (const float*)d_in[8];
    const float* bf   = (const float*)d_in[9];
    const float* Wi   = (const float*)d_in[10];
    const float* bi   = (const float*)d_in[11];
    const float* lng  = (const float*)d_in[12];
    const float* lnb  = (const float*)d_in[13];
    const float* Wout = (const float*)d_in[14];
    const float* bout = (const float*)d_in[15];
    float* out = (float*)d_out;

    __half *W1T, *WgT, *WoutT, *xc, *hid;
    float *gates, *bg;
    cudaGetSymbolAddress((void**)&W1T, g_W1T);
    cudaGetSymbolAddress((void**)&WgT, g_WgT);
    cudaGetSymbolAddress((void**)&WoutT, g_WoutT);
    cudaGetSymbolAddress((void**)&xc, g_xc);
    cudaGetSymbolAddress((void**)&hid, g_hidden);
    cudaGetSymbolAddress((void**)&gates, g_gates);
    cudaGetSymbolAddress((void**)&bg, g_bg);

    cudaFuncSetAttribute(gemm_hmma, cudaFuncAttributeMaxDynamicSharedMemorySize, SMEM_GEMM);

    // ---- weight conversions (fp32 [K][N] -> fp16 [N][K]) ----
    for (int l = 0; l < L_NUM; l++) {
        convT<<<dim3(H_DIM / 32, 2048 / 32), 256>>>(
            W1 + (size_t)l * 2048 * H_DIM, W1T + (size_t)l * H_DIM * 2048, 2048, H_DIM);
        if (l < L_NUM - 1) {
            const float* Ws[3] = { Wd, Wf, Wi };
            for (int gI = 0; gI < 3; gI++)
                convT<<<dim3(C_DIM / 32, H_DIM / 32), 256>>>(
                    Ws[gI] + (size_t)l * H_DIM * C_DIM,
                    WgT + ((size_t)l * 3072 + (size_t)gI * 1024) * H_DIM, H_DIM, C_DIM);
        }
    }
    convT<<<dim3(V_DIM / 32, H_DIM / 32), 256>>>(Wout, WoutT, H_DIM, V_DIM);

    embed_ln_kernel<<<N_TOK, 256>>>(ids, emb, en_g, en_b);

    dim3 gH(N_TOK / 128, H_DIM / 128);   // (32, 32)
    dim3 gG(N_TOK / 128, 3072 / 128);    // (32, 24)
    dim3 gV(N_TOK / 128, V_DIM / 128);   // (32, 250)

    for (int l = 0; l < L_NUM; l++) {
        int Keff = (l == 0) ? E_DIM : 2048;
        gemm_hmma<<<gH, 256, SMEM_GEMM>>>(
            xc, 2048, W1T + (size_t)l * H_DIM * 2048, 2048,
            b1 + (size_t)l * H_DIM, hid, H_DIM, Keff, 1);

        if (l < L_NUM - 1) {
            catbias<<<12, 256>>>(bd + (size_t)l * C_DIM, bf + (size_t)l * C_DIM,
                                 bi + (size_t)l * C_DIM);
            gemm_hmma<<<gG, 256, SMEM_GEMM>>>(
                hid, H_DIM, WgT + (size_t)l * 3072 * H_DIM, H_DIM,
                bg, gates, 3072, H_DIM, 0);
            ctx_kernel<<<N_TOK, 256>>>(lng + (size_t)l * C_DIM, lnb + (size_t)l * C_DIM);
        }
    }

    gemm_hmma<<<gV, 256, SMEM_GEMM>>>(hid, H_DIM, WoutT, H_DIM, bout, out, V_DIM, H_DIM, 0);
}